// round 15
// baseline (speedup 1.0000x reference)
#include <cuda_runtime.h>
#include <cuda_bf16.h>
#include <math.h>
#include <cstdint>

// Problem constants (match reference setup_inputs)
#define NN 100000      // nodes
#define NE 1600000     // edges
#define CH 128         // channels (in == hid)

#define BST 136        // padded bf16 row stride for SMEM A tiles (bank-conflict-free)
#define SCAN_B 1024    // scan block size
#define MAX_BLKS 128   // >= ceil(NN/SCAN_B)

// ---------------- scratch (no allocations allowed) ----------------
__device__ float g_agg[(size_t)NN * CH];
__device__ float g_h  [(size_t)NN * CH];
__device__ float g_z  [(size_t)NN * CH];
__device__ float g_inv[NN];
__device__ int   g_deg[NN];
__device__ int   g_rank[NE];
__device__ int   g_off[NN + 1];
__device__ int   g_bsum[MAX_BLKS];
__device__ int   g_boff[MAX_BLKS];
__device__ int   g_csr_src[NE];
__device__ float g_csr_w[NE];
// B in mma-fragment layout: [matrix(4)][split(2)][ks(8)][nb(16)][lane(32)][2] uint32
__device__ uint32_t g_bfrag[4 * 2 * 8 * 16 * 32 * 2];

// ---------------- SMEM layout for tgemm (bytes) ----------------
#define SM3_BIAS 0                        // 128 f32 = 512 B
#define SM3_AHI  512
#define SM3_ALO  (SM3_AHI + 128 * BST * 2)
#define SM3_TOTAL (SM3_ALO + 128 * BST * 2)   // 70144 B -> 2 CTAs/SM

// ---------------- bf16 mma.sync (baseline PTX, valid at compute_103) ----------------
__device__ __forceinline__ void mma_bf16(float* c, const uint32_t* a, const uint32_t* b) {
    asm volatile(
        "mma.sync.aligned.m16n8k16.row.col.f32.bf16.bf16.f32 "
        "{%0,%1,%2,%3}, {%4,%5,%6,%7}, {%8,%9}, {%0,%1,%2,%3};"
        : "+f"(c[0]), "+f"(c[1]), "+f"(c[2]), "+f"(c[3])
        : "r"(a[0]), "r"(a[1]), "r"(a[2]), "r"(a[3]), "r"(b[0]), "r"(b[1]));
}

// ---------------- prep: weights -> B fragments (hi/lo split, mma layout) ----------------
// fragment uint32 j for (nb,lane,ks): packs bf16{B[n][k], B[n][k+1]},
// n = nb*8 + lane/4, k = ks*16 + (lane%4)*2 + j*8, B[n][k] = W[k][n]
__global__ void prep_bfrag_kernel(const float* __restrict__ w1_rel, const float* __restrict__ w1_root,
                                  const float* __restrict__ w2_rel, const float* __restrict__ w2_root) {
    int idx = blockIdx.x * blockDim.x + threadIdx.x;
    if (idx >= 4 * 2 * 8 * 16 * 32 * 2) return;
    int j    = idx & 1;
    int lane = (idx >> 1) & 31;
    int nb   = (idx >> 6) & 15;
    int ks   = (idx >> 10) & 7;
    int spl  = (idx >> 13) & 1;
    int m    = (idx >> 14) & 3;
    const float* W = (m == 0) ? w1_rel : (m == 1) ? w1_root : (m == 2) ? w2_rel : w2_root;
    int n = nb * 8 + (lane >> 2);
    int k = ks * 16 + (lane & 3) * 2 + j * 8;
    float w0 = W[k * 128 + n];
    float w1 = W[(k + 1) * 128 + n];
    __nv_bfloat16 h0 = __float2bfloat16(w0);
    __nv_bfloat16 h1 = __float2bfloat16(w1);
    __nv_bfloat162 v;
    if (spl == 0) {
        v = __nv_bfloat162(h0, h1);
    } else {
        v = __nv_bfloat162(__float2bfloat16(w0 - __bfloat162float(h0)),
                           __float2bfloat16(w1 - __bfloat162float(h1)));
    }
    g_bfrag[idx] = *reinterpret_cast<uint32_t*>(&v);
}

// ---------------- tensor-core GraphConv linear (mma.sync bf16 2-split) ----------------
// out = g_agg @ Wrel + A2 @ Wroot + bias (+ReLU). B frags from gmem (L2-resident).
__global__ __launch_bounds__(256) void tgemm_kernel(
    const float* __restrict__ A2in, const float* __restrict__ bias,
    int M, int relu, int out_sel, int layer) {
    extern __shared__ char smem[];
    const float* A2 = A2in ? A2in : g_h;
    float* outg = (out_sel == 0) ? g_h : g_z;
    int tid = threadIdx.x;
    int wid = tid >> 5;
    int lane = tid & 31;
    int g = lane >> 2;        // group 0..7
    int tig = lane & 3;       // thread-in-group
    int m0 = blockIdx.x * 128;
    int wm = (wid & 3) * 32;  // warp m offset
    int wnb = (wid >> 2) * 8; // warp n-block base (each block = 8 cols)

    __nv_bfloat16* Ah = (__nv_bfloat16*)(smem + SM3_AHI);
    __nv_bfloat16* Al = (__nv_bfloat16*)(smem + SM3_ALO);
    float* bs = (float*)(smem + SM3_BIAS);

    if (tid < 128) bs[tid] = bias[tid];

    float acc[2][8][4];
#pragma unroll
    for (int i = 0; i < 2; i++)
#pragma unroll
        for (int j = 0; j < 8; j++)
#pragma unroll
            for (int q = 0; q < 4; q++) acc[i][j][q] = 0.0f;

    for (int kh = 0; kh < 2; kh++) {
        const float* S = (kh == 0) ? g_agg : A2;
        if (kh == 1) __syncthreads();   // all warps done reading kh=0 tiles
        // ---- stage A: fp32 -> bf16 hi/lo, row-major padded ----
#pragma unroll
        for (int it = 0; it < 8; it++) {
            int gg = it * 256 + tid;       // granule 0..2047 (8 cols each)
            int row = gg >> 4;
            int col = (gg & 15) * 8;
            float4 v0 = make_float4(0.f, 0.f, 0.f, 0.f);
            float4 v1 = make_float4(0.f, 0.f, 0.f, 0.f);
            int grow = m0 + row;
            if (grow < M) {
                const float* p = S + (size_t)grow * CH + col;
                v0 = reinterpret_cast<const float4*>(p)[0];
                v1 = reinterpret_cast<const float4*>(p)[1];
            }
            float a[8] = {v0.x, v0.y, v0.z, v0.w, v1.x, v1.y, v1.z, v1.w};
            uint32_t hu[4], lu[4];
#pragma unroll
            for (int j = 0; j < 4; j++) {
                __nv_bfloat162 hh = __floats2bfloat162_rn(a[2 * j], a[2 * j + 1]);
                float2 hf = __bfloat1622float2(hh);
                __nv_bfloat162 ll = __floats2bfloat162_rn(a[2 * j] - hf.x, a[2 * j + 1] - hf.y);
                hu[j] = *reinterpret_cast<uint32_t*>(&hh);
                lu[j] = *reinterpret_cast<uint32_t*>(&ll);
            }
            int off = row * BST + col;
            *reinterpret_cast<uint4*>(Ah + off) = make_uint4(hu[0], hu[1], hu[2], hu[3]);
            *reinterpret_cast<uint4*>(Al + off) = make_uint4(lu[0], lu[1], lu[2], lu[3]);
        }
        __syncthreads();

        // ---- compute: 3 splits x 8 ksteps x (2m x 8n) mma; B frags from gmem ----
        int mat = layer * 2 + kh;
#pragma unroll
        for (int sp = 0; sp < 3; sp++) {
            const __nv_bfloat16* As = (sp == 2) ? Al : Ah;
            int spl = (sp == 1) ? 1 : 0;
            const uint32_t* bf_sp = g_bfrag + (size_t)(mat * 2 + spl) * (8 * 16 * 32 * 2);
#pragma unroll
            for (int ks = 0; ks < 8; ks++) {
                int k0 = ks * 16;
                uint32_t afr[2][4];
#pragma unroll
                for (int mi = 0; mi < 2; mi++) {
                    int rb = wm + mi * 16;
                    const __nv_bfloat16* p0 = As + (rb + g) * BST + k0 + tig * 2;
                    const __nv_bfloat16* p1 = As + (rb + g + 8) * BST + k0 + tig * 2;
                    afr[mi][0] = *reinterpret_cast<const uint32_t*>(p0);
                    afr[mi][1] = *reinterpret_cast<const uint32_t*>(p1);
                    afr[mi][2] = *reinterpret_cast<const uint32_t*>(p0 + 8);
                    afr[mi][3] = *reinterpret_cast<const uint32_t*>(p1 + 8);
                }
                uint32_t bfr[8][2];
                const uint32_t* bf_ks = bf_sp + ks * (16 * 32 * 2);
#pragma unroll
                for (int ni = 0; ni < 8; ni++) {
                    // coalesced LDG.64: lane*2 consecutive uint32
                    unsigned long long bb =
                        *reinterpret_cast<const unsigned long long*>(
                            bf_ks + ((wnb + ni) * 32 + lane) * 2);
                    bfr[ni][0] = (uint32_t)bb;
                    bfr[ni][1] = (uint32_t)(bb >> 32);
                }
#pragma unroll
                for (int mi = 0; mi < 2; mi++)
#pragma unroll
                    for (int ni = 0; ni < 8; ni++)
                        mma_bf16(acc[mi][ni], afr[mi], bfr[ni]);
            }
        }
    }

    // ---- epilogue: bias (+ReLU), direct STG ----
#pragma unroll
    for (int mi = 0; mi < 2; mi++) {
        int rb = m0 + wm + mi * 16;
#pragma unroll
        for (int ni = 0; ni < 8; ni++) {
            int col = wnb * 8 + ni * 8 + tig * 2;
            float b0 = bs[col], b1 = bs[col + 1];
            int r0 = rb + g, r1 = rb + g + 8;
            float2 v;
            if (r0 < M) {
                v.x = acc[mi][ni][0] + b0;
                v.y = acc[mi][ni][1] + b1;
                if (relu) { v.x = fmaxf(v.x, 0.f); v.y = fmaxf(v.y, 0.f); }
                *reinterpret_cast<float2*>(outg + (size_t)r0 * CH + col) = v;
            }
            if (r1 < M) {
                v.x = acc[mi][ni][2] + b0;
                v.y = acc[mi][ni][3] + b1;
                if (relu) { v.x = fmaxf(v.x, 0.f); v.y = fmaxf(v.y, 0.f); }
                *reinterpret_cast<float2*>(outg + (size_t)r1 * CH + col) = v;
            }
        }
    }
}

// ---------------- CSR build ----------------
__global__ void zero_deg_kernel(int n) {
    int i = blockIdx.x * blockDim.x + threadIdx.x;
    int stride = gridDim.x * blockDim.x;
    for (; i < n; i += stride) g_deg[i] = 0;
}
// hist also records each edge's rank within its dst (atomicAdd return)
__global__ void hist_kernel(const int* __restrict__ dst, int E) {
    int i = blockIdx.x * blockDim.x + threadIdx.x;
    int stride = gridDim.x * blockDim.x;
    for (; i < E; i += stride) g_rank[i] = atomicAdd(&g_deg[dst[i]], 1);
}

// ---- hierarchical scan: coalesced ----
__global__ __launch_bounds__(SCAN_B) void reduce_kernel(int N) {
    __shared__ int sh[SCAN_B];
    int t = threadIdx.x;
    int i = blockIdx.x * SCAN_B + t;
    sh[t] = (i < N) ? g_deg[i] : 0;
    __syncthreads();
    for (int o = SCAN_B / 2; o > 0; o >>= 1) {
        if (t < o) sh[t] += sh[t + o];
        __syncthreads();
    }
    if (t == 0) g_bsum[blockIdx.x] = sh[0];
}
__global__ __launch_bounds__(MAX_BLKS) void scan_tops_kernel(int nblk, int N, int E) {
    __shared__ int sh[MAX_BLKS];
    int t = threadIdx.x;
    sh[t] = (t < nblk) ? g_bsum[t] : 0;
    __syncthreads();
    for (int o = 1; o < MAX_BLKS; o <<= 1) {
        int v = (t >= o) ? sh[t - o] : 0;
        __syncthreads();
        sh[t] += v;
        __syncthreads();
    }
    if (t < nblk) g_boff[t] = (t > 0) ? sh[t - 1] : 0;
    if (t == 0) g_off[N] = E;
}
__global__ __launch_bounds__(SCAN_B) void scan_block_kernel(int N) {
    __shared__ int sh[SCAN_B];
    int t = threadIdx.x;
    int i = blockIdx.x * SCAN_B + t;
    int d = (i < N) ? g_deg[i] : 0;
    sh[t] = d;
    __syncthreads();
    for (int o = 1; o < SCAN_B; o <<= 1) {
        int v = (t >= o) ? sh[t - o] : 0;
        __syncthreads();
        sh[t] += v;
        __syncthreads();
    }
    if (i < N) {
        g_off[i] = g_boff[blockIdx.x] + sh[t] - d;
        g_inv[i] = 1.0f / fmaxf((float)d, 1.0f);
    }
}

// fill without atomics: position = offset + recorded rank
__global__ void fill_kernel(const int* __restrict__ src,
                            const int* __restrict__ dst,
                            const float* __restrict__ ew, int E) {
    int i = blockIdx.x * blockDim.x + threadIdx.x;
    int stride = gridDim.x * blockDim.x;
    for (; i < E; i += stride) {
        int pos = g_off[dst[i]] + g_rank[i];
        g_csr_src[pos] = src[i];
        g_csr_w[pos]   = ew[i];
    }
}

// ---------------- gather aggregation (mean folded in) ----------------
__global__ void agg_kernel(const float* __restrict__ feat, int N) {
    const float* f = feat ? feat : g_h;
    int lane = threadIdx.x & 31;
    int warp = (blockIdx.x * blockDim.x + threadIdx.x) >> 5;
    int nwarp = (gridDim.x * blockDim.x) >> 5;
    for (int n = warp; n < N; n += nwarp) {
        int start = g_off[n];
        int end   = g_off[n + 1];
        float4 acc0 = make_float4(0.f, 0.f, 0.f, 0.f);
        float4 acc1 = make_float4(0.f, 0.f, 0.f, 0.f);
        int e = start;
        for (; e + 1 < end; e += 2) {
            int   s0 = g_csr_src[e];
            float w0 = g_csr_w[e];
            int   s1 = g_csr_src[e + 1];
            float w1 = g_csr_w[e + 1];
            float4 v0 = reinterpret_cast<const float4*>(f + (size_t)s0 * CH)[lane];
            float4 v1 = reinterpret_cast<const float4*>(f + (size_t)s1 * CH)[lane];
            acc0.x += v0.x * w0; acc0.y += v0.y * w0;
            acc0.z += v0.z * w0; acc0.w += v0.w * w0;
            acc1.x += v1.x * w1; acc1.y += v1.y * w1;
            acc1.z += v1.z * w1; acc1.w += v1.w * w1;
        }
        if (e < end) {
            int   s0 = g_csr_src[e];
            float w0 = g_csr_w[e];
            float4 v0 = reinterpret_cast<const float4*>(f + (size_t)s0 * CH)[lane];
            acc0.x += v0.x * w0; acc0.y += v0.y * w0;
            acc0.z += v0.z * w0; acc0.w += v0.w * w0;
        }
        float inv = g_inv[n];
        float4 r;
        r.x = (acc0.x + acc1.x) * inv;
        r.y = (acc0.y + acc1.y) * inv;
        r.z = (acc0.z + acc1.z) * inv;
        r.w = (acc0.w + acc1.w) * inv;
        reinterpret_cast<float4*>(g_agg + (size_t)n * CH)[lane] = r;
    }
}

// ---------------- decoder: pair dot products ----------------
__global__ void decode_kernel(const int* __restrict__ ps,
                              const int* __restrict__ pd,
                              float* __restrict__ out, int P) {
    int lane = threadIdx.x & 31;
    int warp = (blockIdx.x * blockDim.x + threadIdx.x) >> 5;
    int nwarp = (gridDim.x * blockDim.x) >> 5;
    const float inv_scale = 0.08838834764831845f;  // 1/sqrt(128)
    for (int p = warp; p < P; p += nwarp) {
        int s = ps[p];
        int d = pd[p];
        float4 a = reinterpret_cast<const float4*>(g_z + (size_t)s * CH)[lane];
        float4 b = reinterpret_cast<const float4*>(g_z + (size_t)d * CH)[lane];
        float sum = a.x * b.x + a.y * b.y + a.z * b.z + a.w * b.w;
#pragma unroll
        for (int o = 16; o; o >>= 1) sum += __shfl_xor_sync(0xFFFFFFFFu, sum, o);
        if (lane == 0) out[p] = sum * inv_scale;
    }
}

// ---------------- launch ----------------
extern "C" void kernel_launch(void* const* d_in, const int* in_sizes, int n_in,
                              void* d_out, int out_size) {
    const float* x       = (const float*)d_in[0];
    const int*   ei      = (const int*)d_in[1];
    const float* ew      = (const float*)d_in[2];
    const int*   eli     = (const int*)d_in[3];
    const float* w1_rel  = (const float*)d_in[4];
    const float* b1_rel  = (const float*)d_in[5];
    const float* w1_root = (const float*)d_in[6];
    const float* w2_rel  = (const float*)d_in[7];
    const float* b2_rel  = (const float*)d_in[8];
    const float* w2_root = (const float*)d_in[9];
    float* out = (float*)d_out;

    const int N = in_sizes[0] / CH;
    const int E = in_sizes[2];
    const int P = in_sizes[3] / 2;

    const int* src = ei;
    const int* dst = ei + E;
    const int* ps  = eli;
    const int* pd  = eli + P;

    const int egrid = (E + 255) / 256;
    const int ngrid = (N + 255) / 256;
    const int agrid = (N * 32 + 255) / 256;
    const int tgrid = (N + 127) / 128;
    const int sblk  = (N + SCAN_B - 1) / SCAN_B;
    const int nfrag = 4 * 2 * 8 * 16 * 32 * 2;

    cudaFuncSetAttribute(tgemm_kernel, cudaFuncAttributeMaxDynamicSharedMemorySize, SM3_TOTAL);

    // ---- weight prep + CSR build ----
    prep_bfrag_kernel<<<(nfrag + 255) / 256, 256>>>(w1_rel, w1_root, w2_rel, w2_root);
    zero_deg_kernel<<<ngrid, 256>>>(N);
    hist_kernel<<<egrid, 256>>>(dst, E);
    reduce_kernel<<<sblk, SCAN_B>>>(N);
    scan_tops_kernel<<<1, MAX_BLKS>>>(sblk, N, E);
    scan_block_kernel<<<sblk, SCAN_B>>>(N);
    fill_kernel<<<egrid, 256>>>(src, dst, ew, E);

    // ---- layer 1 ----
    agg_kernel<<<agrid, 256>>>(x, N);
    tgemm_kernel<<<tgrid, 256, SM3_TOTAL>>>(x, b1_rel, N, /*relu=*/1, /*out=h*/0, /*layer=*/0);

    // ---- layer 2 ----
    agg_kernel<<<agrid, 256>>>(nullptr, N);
    tgemm_kernel<<<tgrid, 256, SM3_TOTAL>>>(nullptr, b2_rel, N, /*relu=*/0, /*out=z*/1, /*layer=*/1);

    // ---- decode ----
    decode_kernel<<<2048, 256>>>(ps, pd, out, P);
}